// round 6
// baseline (speedup 1.0000x reference)
#include <cuda_runtime.h>

// Fused beam reorder + suffix append for KV cache.
// Shapes: L=8, G=128, NH=8, T=128, HD=64, fp32.
//   out_k[l,g,h,t,:] = (t==pos) ? k_new[l,g,h,0,:] : k_buf[l,beam[g],h,t,:]
//   out_v analogous. Output = [k ; v] concatenated.
//
// float4 (16B) units: NEL4 = 2^24 per buffer; beam stride = 2^14.
//   t=(j>>4)&127; g=(j>>14)&127; gather src = j + (beam[g]-g)<<14
//   append src = ((j>>11)<<4)|(j&15)   ({k,v}_new is [L,G,NH,1,HD])
//
// Converged design notes (R2-R5 evidence):
//  - Compulsory traffic ≈ 836 MB (512 MB writes + unique-beam reads; L2
//    dedups duplicate beams with or without block reordering).
//  - Sustained ~6.52-6.55 TB/s across ILP/cache-policy/order variants =>
//    that's the mixed-stream HBM ceiling; MLP>4 and L2 scheduling are
//    non-levers. Single launch minimizes fixed overhead.
//
// Each block moves one 1024-float4 chunk of BOTH k and v (two independent
// read streams, 8 front-batched LDG.128). grid = 16384.

static constexpr unsigned NEL4  = 1u << 24;   // float4s per buffer
static constexpr int      ILP   = 4;
static constexpr int      THREADS = 256;
static constexpr unsigned CHUNK = THREADS * ILP;          // 1024 float4
static constexpr unsigned BLOCKS = NEL4 / CHUNK;          // 16384

__global__ void __launch_bounds__(THREADS, 8)
beam_reorder_append_kernel(const float4* __restrict__ kb,
                           const float4* __restrict__ vb,
                           const float4* __restrict__ kn,
                           const float4* __restrict__ vn,
                           const int*    __restrict__ beam,
                           const int*    __restrict__ posp,
                           float4*       __restrict__ out)
{
    const unsigned jbase = blockIdx.x * CHUNK;            // 1024-aligned
    const int pos = *posp;                                // L1-hit, uniform
    const unsigned g = (jbase >> 14) & 127;               // uniform per block
    const unsigned delta = ((unsigned)(beam[g] - (int)g)) << 14;  // uniform

    float4 rk[ILP], rv[ILP];

    // Front-batch 8 independent 128-bit loads: 4 from k, 4 from v
    // (two read streams 256 MB apart -> spread across L2 slices/channels).
    #pragma unroll
    for (int k = 0; k < ILP; k++) {
        const unsigned j = jbase + threadIdx.x + (unsigned)k * THREADS;
        const unsigned t = (j >> 4) & 127;
        const bool app = (t == (unsigned)pos);
        const unsigned sidx = app ? (((j >> 11) << 4) | (j & 15))
                                  : (j + delta);
        rk[k] = __ldg((app ? kn : kb) + sidx);
        rv[k] = __ldg((app ? vn : vb) + sidx);
    }

    // Streaming stores: output never re-read.
    #pragma unroll
    for (int k = 0; k < ILP; k++) {
        const unsigned o = jbase + threadIdx.x + (unsigned)k * THREADS;
        __stcs(out + o,        rk[k]);
        __stcs(out + o + NEL4, rv[k]);
    }
}

extern "C" void kernel_launch(void* const* d_in, const int* in_sizes, int n_in,
                              void* d_out, int out_size)
{
    const float4* kb   = (const float4*)d_in[0];  // k_buf  [L,G,NH,T,HD] fp32
    const float4* vb   = (const float4*)d_in[1];  // v_buf
    const float4* kn   = (const float4*)d_in[2];  // k_new  [L,G,NH,1,HD]
    const float4* vn   = (const float4*)d_in[3];  // v_new
    const int*    beam = (const int*)d_in[4];     // new_beam_idx [G]
    const int*    posp = (const int*)d_in[5];     // pos (scalar, device-side)
    float4*       out  = (float4*)d_out;          // [2,L,G,NH,T,HD] fp32

    beam_reorder_append_kernel<<<BLOCKS, THREADS>>>(
        kb, vb, kn, vn, beam, posp, out);
}

// round 7
// speedup vs baseline: 1.0182x; 1.0182x over previous
#include <cuda_runtime.h>

// Fused beam reorder + suffix append for KV cache.  [CONVERGED — R4 config]
// Shapes: L=8, G=128, NH=8, T=128, HD=64, fp32.
//   out_k[l,g,h,t,:] = (t==pos) ? k_new[l,g,h,0,:] : k_buf[l,beam[g],h,t,:]
//   out_v analogous. Output = [k ; v] concatenated.
//
// float4 (16B) units: NEL4 = 2^24 per buffer; beam stride = 2^14.
//   t=(j>>4)&127; g=(j>>14)&127; gather src = j + (beam[g]-g)<<14
//   append src = ((j>>11)<<4)|(j&15)   ({k,v}_new is [L,G,NH,1,HD])
//
// Convergence evidence (R1-R6):
//  - Compulsory traffic ≈ 836 MB (512 MB writes + unique-beam reads;
//    E[unique beams]≈81/128, L2 dedups duplicates regardless of block order).
//  - Measured 6.51-6.55 TB/s across ILP{1,4,8}, cache policies, beam-sorted
//    ordering, and K+V fusion => mixed-stream HBM ceiling. ILP=4 with one
//    launch is the fastest measured point (kernel 130.5 us).
//
// Block = 256 thr x ILP 4 = 1024 contiguous float4, 1024-aligned.
// 1024 | 2^14 => g, is_v, and the beam delta are uniform per block.

static constexpr unsigned NEL4  = 1u << 24;      // float4s per buffer
static constexpr unsigned TOTAL = 1u << 25;      // k + v
static constexpr int      ILP   = 4;
static constexpr int      THREADS = 256;

__global__ void __launch_bounds__(THREADS, 8)
beam_reorder_append_kernel(const float4* __restrict__ kb,
                           const float4* __restrict__ vb,
                           const float4* __restrict__ kn,
                           const float4* __restrict__ vn,
                           const int*    __restrict__ beam,
                           const int*    __restrict__ posp,
                           float4*       __restrict__ out)
{
    const unsigned base = blockIdx.x * (THREADS * ILP);   // 1024-aligned
    const bool is_v = base >= NEL4;                       // uniform per block
    const unsigned jbase = base & (NEL4 - 1);

    const int pos = *posp;                                // L1-hit, uniform
    const unsigned g = (jbase >> 14) & 127;               // uniform per block
    const unsigned delta = ((unsigned)(beam[g] - (int)g)) << 14;  // uniform

    const float4* __restrict__ buf  = is_v ? vb : kb;
    const float4* __restrict__ nbuf = is_v ? vn : kn;

    float4 r[ILP];

    // Front-batch all 4 independent 128-bit loads (MLP_p1 = 4).
    // Default cache policy: duplicate-beam lines stay L2-resident for dedup.
    #pragma unroll
    for (int k = 0; k < ILP; k++) {
        const unsigned j = jbase + threadIdx.x + (unsigned)k * THREADS;
        const unsigned t = (j >> 4) & 127;
        const bool app = (t == (unsigned)pos);
        const unsigned sidx = app ? (((j >> 11) << 4) | (j & 15))
                                  : (j + delta);
        const float4* __restrict__ src = app ? nbuf : buf;
        r[k] = __ldg(src + sidx);
    }

    // Streaming stores: output never re-read, evict-first.
    #pragma unroll
    for (int k = 0; k < ILP; k++)
        __stcs(out + base + threadIdx.x + (unsigned)k * THREADS, r[k]);
}

extern "C" void kernel_launch(void* const* d_in, const int* in_sizes, int n_in,
                              void* d_out, int out_size)
{
    const float4* kb   = (const float4*)d_in[0];  // k_buf  [L,G,NH,T,HD] fp32
    const float4* vb   = (const float4*)d_in[1];  // v_buf
    const float4* kn   = (const float4*)d_in[2];  // k_new  [L,G,NH,1,HD]
    const float4* vn   = (const float4*)d_in[3];  // v_new
    const int*    beam = (const int*)d_in[4];     // new_beam_idx [G]
    const int*    posp = (const int*)d_in[5];     // pos (scalar, device-side)
    float4*       out  = (float4*)d_out;          // [2,L,G,NH,T,HD] fp32

    const unsigned blocks = TOTAL / (THREADS * ILP);      // 32768
    beam_reorder_append_kernel<<<blocks, THREADS>>>(
        kb, vb, kn, vn, beam, posp, out);
}